// round 14
// baseline (speedup 1.0000x reference)
#include <cuda_runtime.h>
#include <cuda_fp16.h>
#include <cstdint>

// ---------------------------------------------------------------------------
// MockLoHAAdapter: y = x @ (W + (w1a@w1b)*(w2a@w2b)*scalar)^T + bias
// Round 12: (1) fused prep+convert kernel (grid-partitioned);
// (2) GEMM BM=256 x BN=128, 512 threads (16 warps = 4/SMSP), 3-stage
// cp.async, ldmatrix frags. Barrier amortized over 2x tile at same
// warps-per-SMSP as round 9.
// ---------------------------------------------------------------------------

#define IN_DIM   4096
#define OUT_DIM  4096
#define RANK     16
#define M_TOTAL  8192

#define BM        256
#define BN        128
#define BK        64                     // halfs per k-tile -> 128 B/row
#define NT        (IN_DIM / BK)          // 64 k-tiles
#define NSTAGE    3
#define ROW_HALFS 72                     // 64 + 8 pad (144 B, 16B-aligned)
#define A_HALFS   (BM * ROW_HALFS)       // 18432
#define B_HALFS   (BN * ROW_HALFS)       // 9216
#define STAGE_HALFS (A_HALFS + B_HALFS)  // 27648
#define SMEM_BYTES  (NSTAGE * STAGE_HALFS * 2)   // 165888

#define CONV_BLOCKS 2048                 // x-convert blocks (8M float4 / 4096)
#define PREP_BLOCKS 512                  // 16 i-tiles x 32 o-tiles

// Device-global fp16 operands (allocation-free rule).
__device__ __half g_Wh[(size_t)OUT_DIM * IN_DIM];
__device__ __half g_Xh[(size_t)M_TOTAL * IN_DIM];

// ---------------------------------------------------------------------------
// Kernel 1 (fused): blocks [0, CONV_BLOCKS) convert x -> fp16;
// blocks [CONV_BLOCKS, +PREP_BLOCKS) compute Wc -> fp16 (round-9 prep body).
// ---------------------------------------------------------------------------
__global__ __launch_bounds__(256) void prep_fused_kernel(
    const float* __restrict__ x,
    const float* __restrict__ W,
    const float* __restrict__ w1a, const float* __restrict__ w1b,
    const float* __restrict__ w2a, const float* __restrict__ w2b,
    const float* __restrict__ scalar)
{
    __shared__ float b1s[RANK][256];
    __shared__ float b2s[RANK][256];
    __shared__ __align__(16) float a1s[128][RANK];
    __shared__ __align__(16) float a2s[128][RANK];

    const int tid = threadIdx.x;

    if (blockIdx.x < CONV_BLOCKS) {
        // ---- convert x: 4096 float4 per block, 16 per thread ----
        const size_t base = (size_t)blockIdx.x * 4096;
#pragma unroll
        for (int j = 0; j < 16; j++) {
            const size_t i = base + j * 256 + tid;
            const float4 v = __ldg(reinterpret_cast<const float4*>(x) + i);
            const __half2 h0 = __floats2half2_rn(v.x, v.y);
            const __half2 h1 = __floats2half2_rn(v.z, v.w);
            uint2 o;
            o.x = *reinterpret_cast<const uint32_t*>(&h0);
            o.y = *reinterpret_cast<const uint32_t*>(&h1);
            reinterpret_cast<uint2*>(g_Xh)[i] = o;
        }
        return;
    }

    // ---- prep weight (round-9 structure: i-tile 256, o-tile 128) ----
    const int pid = blockIdx.x - CONV_BLOCKS;
    const int i0 = (pid & 15) * 256;         // 16 i-tiles
    const int o0 = (pid >> 4) * 128;         // 32 o-tiles
    const float s = scalar[0];

#pragma unroll
    for (int j = 0; j < RANK; j++) {
        b1s[j][tid] = w1b[j * IN_DIM + i0 + tid];
        b2s[j][tid] = w2b[j * IN_DIM + i0 + tid];
    }
#pragma unroll
    for (int j = 0; j < 8; j++) {
        const int idx = j * 256 + tid;
        a1s[idx >> 4][idx & 15] = w1a[(o0 + (idx >> 4)) * RANK + (idx & 15)];
        a2s[idx >> 4][idx & 15] = w2a[(o0 + (idx >> 4)) * RANK + (idx & 15)];
    }
    __syncthreads();

    float b1v[RANK], b2v[RANK];
#pragma unroll
    for (int r = 0; r < RANK; r++) { b1v[r] = b1s[r][tid]; b2v[r] = b2s[r][tid]; }

    for (int o = 0; o < 128; o++) {
        const float4* a1p = reinterpret_cast<const float4*>(a1s[o]);
        const float4* a2p = reinterpret_cast<const float4*>(a2s[o]);
        float s1 = 0.f, s2 = 0.f;
#pragma unroll
        for (int q = 0; q < 4; q++) {
            const float4 a1 = a1p[q];
            const float4 a2 = a2p[q];
            s1 = fmaf(a1.x, b1v[q*4+0], s1); s2 = fmaf(a2.x, b2v[q*4+0], s2);
            s1 = fmaf(a1.y, b1v[q*4+1], s1); s2 = fmaf(a2.y, b2v[q*4+1], s2);
            s1 = fmaf(a1.z, b1v[q*4+2], s1); s2 = fmaf(a2.z, b2v[q*4+2], s2);
            s1 = fmaf(a1.w, b1v[q*4+3], s1); s2 = fmaf(a2.w, b2v[q*4+3], s2);
        }
        const float w = __ldg(&W[(size_t)(o0 + o) * IN_DIM + i0 + tid]);
        g_Wh[(size_t)(o0 + o) * IN_DIM + i0 + tid] = __float2half_rn(w + s1 * s2 * s);
    }
}

// ---------------------------------------------------------------------------
// Kernel 2: fp16 GEMM. BM=256, BN=128, BK=64, 512 thr (16 warps: 4M x 4N,
// warp tile 64x32), ldmatrix frags, 3-stage cp.async, 1 CTA/SM (4 warps/SMSP).
// ---------------------------------------------------------------------------
__device__ __forceinline__ void mma_f16(float c[4], const uint32_t a[4],
                                        uint32_t b0, uint32_t b1) {
    asm volatile(
        "mma.sync.aligned.m16n8k16.row.col.f32.f16.f16.f32 "
        "{%0,%1,%2,%3}, {%4,%5,%6,%7}, {%8,%9}, {%0,%1,%2,%3};"
        : "+f"(c[0]), "+f"(c[1]), "+f"(c[2]), "+f"(c[3])
        : "r"(a[0]), "r"(a[1]), "r"(a[2]), "r"(a[3]), "r"(b0), "r"(b1));
}

__device__ __forceinline__ void ldmatrix_x4(uint32_t& r0, uint32_t& r1,
                                            uint32_t& r2, uint32_t& r3,
                                            uint32_t saddr) {
    asm volatile("ldmatrix.sync.aligned.m8n8.x4.shared.b16 {%0,%1,%2,%3}, [%4];"
                 : "=r"(r0), "=r"(r1), "=r"(r2), "=r"(r3) : "r"(saddr));
}

__device__ __forceinline__ void cp_async16(uint32_t smem_addr, const void* gptr) {
    asm volatile("cp.async.cg.shared.global [%0], [%1], 16;\n"
                 :: "r"(smem_addr), "l"(gptr));
}

__global__ __launch_bounds__(512, 1) void gemm_f16_pipe(
    const float* __restrict__ bias, float* __restrict__ y)
{
    extern __shared__ __align__(16) __half sm[];

    const int tid  = threadIdx.x;
    const int lane = tid & 31;
    const int warp = tid >> 5;
    const int wm   = (warp >> 2) * 64;   // 4 warps in M, 64 rows each
    const int wn   = (warp & 3) * 32;    // 4 warps in N, 32 cols each
    const int lr   = lane >> 2;
    const int lc   = lane & 3;

    const int bm = blockIdx.y;
    const int bn = blockIdx.x;

    const __half* Aptr = g_Xh + (size_t)(bm * BM) * IN_DIM;
    const __half* Bptr = g_Wh + (size_t)(bn * BN) * IN_DIM;

    const uint32_t smem_base = (uint32_t)__cvta_generic_to_shared(sm);

    // Stage fill: A 2048 16B-chunks (4/thread), B 1024 (2/thread).
    auto issue_stage = [&](int kt, int s) {
        const uint32_t st = smem_base + (uint32_t)(s * STAGE_HALFS) * 2;
        const int kofs = kt * BK;
#pragma unroll
        for (int p = 0; p < 4; p++) {
            const int c = p * 512 + tid;
            const int row = c >> 3;
            const int col16 = c & 7;
            const uint32_t so = (uint32_t)(row * ROW_HALFS * 2 + col16 * 16);
            cp_async16(st + so, Aptr + (size_t)row * IN_DIM + kofs + col16 * 8);
        }
#pragma unroll
        for (int p = 0; p < 2; p++) {
            const int c = p * 512 + tid;
            const int row = c >> 3;
            const int col16 = c & 7;
            const uint32_t so = (uint32_t)((BM + row) * ROW_HALFS * 2 + col16 * 16);
            cp_async16(st + so, Bptr + (size_t)row * IN_DIM + kofs + col16 * 8);
        }
    };

    // ldmatrix per-lane selectors.
    const int a_row = (lane & 7) + ((lane & 8) ? 8 : 0);
    const int a_col = (lane & 16) ? 8 : 0;
    const int b_row = (lane & 7) + ((lane & 16) ? 8 : 0);
    const int b_col = (lane & 8) ? 8 : 0;

    float acc[4][4][4];
#pragma unroll
    for (int mi = 0; mi < 4; mi++)
#pragma unroll
        for (int ni = 0; ni < 4; ni++)
#pragma unroll
            for (int q = 0; q < 4; q++) acc[mi][ni][q] = 0.f;

#pragma unroll
    for (int i = 0; i < NSTAGE - 1; i++) {
        issue_stage(i, i);
        asm volatile("cp.async.commit_group;\n" ::);
    }

    for (int kt = 0; kt < NT; kt++) {
        asm volatile("cp.async.wait_group %0;\n" :: "n"(NSTAGE - 2));
        __syncthreads();

        if (kt + NSTAGE - 1 < NT) issue_stage(kt + NSTAGE - 1, (kt + NSTAGE - 1) % NSTAGE);
        asm volatile("cp.async.commit_group;\n" ::);

        const int s = kt % NSTAGE;
        const uint32_t As = smem_base + (uint32_t)(s * STAGE_HALFS) * 2;
        const uint32_t Bs = As + (uint32_t)A_HALFS * 2;

#pragma unroll
        for (int ks = 0; ks < 4; ks++) {
            const int k0 = ks * 16;
            uint32_t a[4][4];
#pragma unroll
            for (int mi = 0; mi < 4; mi++) {
                const uint32_t addr = As +
                    (uint32_t)((wm + mi * 16 + a_row) * ROW_HALFS + k0 + a_col) * 2;
                ldmatrix_x4(a[mi][0], a[mi][1], a[mi][2], a[mi][3], addr);
            }
            uint32_t b[4][2];
#pragma unroll
            for (int np = 0; np < 2; np++) {
                const uint32_t addr = Bs +
                    (uint32_t)((wn + np * 16 + b_row) * ROW_HALFS + k0 + b_col) * 2;
                ldmatrix_x4(b[np * 2][0], b[np * 2][1],
                            b[np * 2 + 1][0], b[np * 2 + 1][1], addr);
            }
#pragma unroll
            for (int mi = 0; mi < 4; mi++)
#pragma unroll
                for (int ni = 0; ni < 4; ni++)
                    mma_f16(acc[mi][ni], a[mi], b[ni][0], b[ni][1]);
        }
    }

    // Epilogue: y = acc + bias
    float* yb = y + (size_t)(bm * BM + wm) * OUT_DIM + bn * BN + wn;
    const float* biasb = bias + bn * BN + wn;
#pragma unroll
    for (int mi = 0; mi < 4; mi++) {
#pragma unroll
        for (int ni = 0; ni < 4; ni++) {
            const int col = ni * 8 + lc * 2;
            const float2 bb = *reinterpret_cast<const float2*>(biasb + col);
            float2 v0 = make_float2(acc[mi][ni][0] + bb.x, acc[mi][ni][1] + bb.y);
            float2 v1 = make_float2(acc[mi][ni][2] + bb.x, acc[mi][ni][3] + bb.y);
            *reinterpret_cast<float2*>(yb + (size_t)(mi * 16 + lr) * OUT_DIM + col)     = v0;
            *reinterpret_cast<float2*>(yb + (size_t)(mi * 16 + lr + 8) * OUT_DIM + col) = v1;
        }
    }
}

// ---------------------------------------------------------------------------
extern "C" void kernel_launch(void* const* d_in, const int* in_sizes, int n_in,
                              void* d_out, int out_size)
{
    const float* x      = (const float*)d_in[0];
    const float* W      = (const float*)d_in[1];
    const float* bias   = (const float*)d_in[2];
    const float* w1a    = (const float*)d_in[3];
    const float* w1b    = (const float*)d_in[4];
    const float* w2a    = (const float*)d_in[5];
    const float* w2b    = (const float*)d_in[6];
    const float* scalar = (const float*)d_in[7];
    float* y = (float*)d_out;

    (void)in_sizes; (void)n_in; (void)out_size;

    static bool attr_set = false;
    if (!attr_set) {
        cudaFuncSetAttribute(gemm_f16_pipe,
                             cudaFuncAttributeMaxDynamicSharedMemorySize, SMEM_BYTES);
        attr_set = true;
    }

    prep_fused_kernel<<<CONV_BLOCKS + PREP_BLOCKS, 256>>>(x, W, w1a, w1b, w2a, w2b, scalar);
    gemm_f16_pipe<<<dim3(OUT_DIM / BN, M_TOTAL / BM), 512, SMEM_BYTES>>>(bias, y);
}

// round 15
// speedup vs baseline: 1.0780x; 1.0780x over previous
#include <cuda_runtime.h>
#include <cuda_fp16.h>
#include <cstdint>

// ---------------------------------------------------------------------------
// MockLoHAAdapter: y = x @ (W + (w1a@w1b)*(w2a@w2b)*scalar)^T + bias
// Round 15: GEMM reverted to proven round-9 config (128x128, BK=64, 3-stage
// cp.async, ldmatrix, 2 CTA/SM). Prep+convert fused into ONE kernel with
// wave-interleaved roles (1 prep : 4 conv) and MLP-4 W loads in prep.
// ---------------------------------------------------------------------------

#define IN_DIM   4096
#define OUT_DIM  4096
#define RANK     16
#define M_TOTAL  8192

#define BK        64                     // halfs per k-tile -> 128 B/row
#define NT        (IN_DIM / BK)          // 64 k-tiles
#define NSTAGE    3
#define ROW_HALFS 72                     // 64 + 8 pad (144 B, 16B-aligned)
#define TILE_HALFS (128 * ROW_HALFS)
#define STAGE_HALFS (2 * TILE_HALFS)     // A + B
#define SMEM_BYTES  (NSTAGE * STAGE_HALFS * 2)   // 110592 -> 2 CTAs/SM

#define FUSED_BLOCKS 2560                // 512 prep + 2048 conv, interleaved 1:4

// Device-global fp16 operands (allocation-free rule).
__device__ __half g_Wh[(size_t)OUT_DIM * IN_DIM];
__device__ __half g_Xh[(size_t)M_TOTAL * IN_DIM];

// ---------------------------------------------------------------------------
// Kernel 1 (fused, wave-interleaved):
//   blockIdx % 5 == 0  -> prep block (pid = blockIdx/5, 512 total):
//       Wc = (W + (w1a@w1b)*(w2a@w2b)*scalar) -> fp16, o-tile 128 x i-tile 256
//   else               -> conv block (cid, 2048 total): x -> fp16, 64KB each
// ---------------------------------------------------------------------------
__global__ __launch_bounds__(256) void prep_fused_kernel(
    const float* __restrict__ x,
    const float* __restrict__ W,
    const float* __restrict__ w1a, const float* __restrict__ w1b,
    const float* __restrict__ w2a, const float* __restrict__ w2b,
    const float* __restrict__ scalar)
{
    __shared__ float b1s[RANK][256];
    __shared__ float b2s[RANK][256];
    __shared__ __align__(16) float a1s[128][RANK];
    __shared__ __align__(16) float a2s[128][RANK];

    const int tid = threadIdx.x;
    const int b   = blockIdx.x;

    if (b % 5 != 0) {
        // ---- convert x: 4096 float4 per block, 16 per thread ----
        const int cid = b - b / 5 - 1;     // 0..2047
        const size_t base = (size_t)cid * 4096;
#pragma unroll
        for (int j = 0; j < 16; j++) {
            const size_t i = base + j * 256 + tid;
            const float4 v = __ldg(reinterpret_cast<const float4*>(x) + i);
            const __half2 h0 = __floats2half2_rn(v.x, v.y);
            const __half2 h1 = __floats2half2_rn(v.z, v.w);
            uint2 o;
            o.x = *reinterpret_cast<const uint32_t*>(&h0);
            o.y = *reinterpret_cast<const uint32_t*>(&h1);
            reinterpret_cast<uint2*>(g_Xh)[i] = o;
        }
        return;
    }

    // ---- prep weight: round-9 structure, o-loop unrolled x4 (MLP-4 W loads) ----
    const int pid = b / 5;                 // 0..511
    const int i0 = (pid & 15) * 256;       // 16 i-tiles
    const int o0 = (pid >> 4) * 128;       // 32 o-tiles
    const float s = scalar[0];

#pragma unroll
    for (int j = 0; j < RANK; j++) {
        b1s[j][tid] = w1b[j * IN_DIM + i0 + tid];
        b2s[j][tid] = w2b[j * IN_DIM + i0 + tid];
    }
#pragma unroll
    for (int j = 0; j < 8; j++) {
        const int idx = j * 256 + tid;
        a1s[idx >> 4][idx & 15] = w1a[(o0 + (idx >> 4)) * RANK + (idx & 15)];
        a2s[idx >> 4][idx & 15] = w2a[(o0 + (idx >> 4)) * RANK + (idx & 15)];
    }
    __syncthreads();

    float b1v[RANK], b2v[RANK];
#pragma unroll
    for (int r = 0; r < RANK; r++) { b1v[r] = b1s[r][tid]; b2v[r] = b2s[r][tid]; }

    for (int o = 0; o < 128; o += 4) {
        float w[4];
#pragma unroll
        for (int j = 0; j < 4; j++)
            w[j] = __ldg(&W[(size_t)(o0 + o + j) * IN_DIM + i0 + tid]);

#pragma unroll
        for (int j = 0; j < 4; j++) {
            const float4* a1p = reinterpret_cast<const float4*>(a1s[o + j]);
            const float4* a2p = reinterpret_cast<const float4*>(a2s[o + j]);
            float s1 = 0.f, s2 = 0.f;
#pragma unroll
            for (int q = 0; q < 4; q++) {
                const float4 a1 = a1p[q];
                const float4 a2 = a2p[q];
                s1 = fmaf(a1.x, b1v[q*4+0], s1); s2 = fmaf(a2.x, b2v[q*4+0], s2);
                s1 = fmaf(a1.y, b1v[q*4+1], s1); s2 = fmaf(a2.y, b2v[q*4+1], s2);
                s1 = fmaf(a1.z, b1v[q*4+2], s1); s2 = fmaf(a2.z, b2v[q*4+2], s2);
                s1 = fmaf(a1.w, b1v[q*4+3], s1); s2 = fmaf(a2.w, b2v[q*4+3], s2);
            }
            g_Wh[(size_t)(o0 + o + j) * IN_DIM + i0 + tid] =
                __float2half_rn(w[j] + s1 * s2 * s);
        }
    }
}

// ---------------------------------------------------------------------------
// Kernel 2: fp16 GEMM (round-9 verbatim). BM=BN=128, BK=64, 256 thr
// (8 warps: 4M x 2N, warp 32x64), ldmatrix frags, 3-stage cp.async, 2 CTA/SM.
// ---------------------------------------------------------------------------
__device__ __forceinline__ void mma_f16(float c[4], const uint32_t a[4],
                                        uint32_t b0, uint32_t b1) {
    asm volatile(
        "mma.sync.aligned.m16n8k16.row.col.f32.f16.f16.f32 "
        "{%0,%1,%2,%3}, {%4,%5,%6,%7}, {%8,%9}, {%0,%1,%2,%3};"
        : "+f"(c[0]), "+f"(c[1]), "+f"(c[2]), "+f"(c[3])
        : "r"(a[0]), "r"(a[1]), "r"(a[2]), "r"(a[3]), "r"(b0), "r"(b1));
}

__device__ __forceinline__ void ldmatrix_x4(uint32_t& r0, uint32_t& r1,
                                            uint32_t& r2, uint32_t& r3,
                                            uint32_t saddr) {
    asm volatile("ldmatrix.sync.aligned.m8n8.x4.shared.b16 {%0,%1,%2,%3}, [%4];"
                 : "=r"(r0), "=r"(r1), "=r"(r2), "=r"(r3) : "r"(saddr));
}

__device__ __forceinline__ void cp_async16(uint32_t smem_addr, const void* gptr) {
    asm volatile("cp.async.cg.shared.global [%0], [%1], 16;\n"
                 :: "r"(smem_addr), "l"(gptr));
}

__global__ __launch_bounds__(256, 2) void gemm_f16_pipe(
    const float* __restrict__ bias, float* __restrict__ y)
{
    extern __shared__ __align__(16) __half sm[];

    const int tid  = threadIdx.x;
    const int lane = tid & 31;
    const int warp = tid >> 5;
    const int wm   = (warp >> 1) * 32;   // warp M offset (4 warps in M)
    const int wn   = (warp & 1) * 64;    // warp N offset (2 warps in N)
    const int lr   = lane >> 2;          // 0..7
    const int lc   = lane & 3;           // 0..3

    const int bm = blockIdx.y;
    const int bn = blockIdx.x;

    const __half* Aptr = g_Xh + (size_t)(bm * 128) * IN_DIM;
    const __half* Bptr = g_Wh + (size_t)(bn * 128) * IN_DIM;

    const uint32_t smem_base = (uint32_t)__cvta_generic_to_shared(sm);

    auto issue_stage = [&](int kt, int s) {
        const uint32_t st = smem_base + (uint32_t)(s * STAGE_HALFS) * 2;
        const int kofs = kt * BK;
#pragma unroll
        for (int p = 0; p < 4; p++) {
            const int c = p * 256 + tid;
            const int row = c >> 3;
            const int col16 = c & 7;
            const uint32_t so = (uint32_t)(row * ROW_HALFS * 2 + col16 * 16);
            const size_t go = (size_t)row * IN_DIM + kofs + col16 * 8;
            cp_async16(st + so,                  Aptr + go);
            cp_async16(st + TILE_HALFS * 2 + so, Bptr + go);
        }
    };

    // ldmatrix per-lane selectors.
    const int a_row = (lane & 7) + ((lane & 8) ? 8 : 0);
    const int a_col = (lane & 16) ? 8 : 0;
    const int b_row = (lane & 7) + ((lane & 16) ? 8 : 0);
    const int b_col = (lane & 8) ? 8 : 0;

    float acc[2][8][4];
#pragma unroll
    for (int mi = 0; mi < 2; mi++)
#pragma unroll
        for (int ni = 0; ni < 8; ni++)
#pragma unroll
            for (int q = 0; q < 4; q++) acc[mi][ni][q] = 0.f;

#pragma unroll
    for (int i = 0; i < NSTAGE - 1; i++) {
        issue_stage(i, i);
        asm volatile("cp.async.commit_group;\n" ::);
    }

    for (int kt = 0; kt < NT; kt++) {
        asm volatile("cp.async.wait_group %0;\n" :: "n"(NSTAGE - 2));
        __syncthreads();

        if (kt + NSTAGE - 1 < NT) issue_stage(kt + NSTAGE - 1, (kt + NSTAGE - 1) % NSTAGE);
        asm volatile("cp.async.commit_group;\n" ::);

        const int s = kt % NSTAGE;
        const uint32_t As = smem_base + (uint32_t)(s * STAGE_HALFS) * 2;
        const uint32_t Bs = As + TILE_HALFS * 2;

#pragma unroll
        for (int ks = 0; ks < 4; ks++) {
            const int k0 = ks * 16;
            uint32_t a[2][4];
#pragma unroll
            for (int mi = 0; mi < 2; mi++) {
                const uint32_t addr = As +
                    (uint32_t)((wm + mi * 16 + a_row) * ROW_HALFS + k0 + a_col) * 2;
                ldmatrix_x4(a[mi][0], a[mi][1], a[mi][2], a[mi][3], addr);
            }
            uint32_t b[8][2];
#pragma unroll
            for (int np = 0; np < 4; np++) {
                const uint32_t addr = Bs +
                    (uint32_t)((wn + np * 16 + b_row) * ROW_HALFS + k0 + b_col) * 2;
                ldmatrix_x4(b[np * 2][0], b[np * 2][1], b[np * 2 + 1][0], b[np * 2 + 1][1], addr);
            }
#pragma unroll
            for (int ni = 0; ni < 8; ni++) {
                mma_f16(acc[0][ni], a[0], b[ni][0], b[ni][1]);
                mma_f16(acc[1][ni], a[1], b[ni][0], b[ni][1]);
            }
        }
    }

    // Epilogue: y = acc + bias
    float* yb = y + (size_t)(bm * 128 + wm) * OUT_DIM + bn * 128 + wn;
    const float* biasb = bias + bn * 128 + wn;
#pragma unroll
    for (int mi = 0; mi < 2; mi++) {
#pragma unroll
        for (int ni = 0; ni < 8; ni++) {
            const int col = ni * 8 + lc * 2;
            const float2 bb = *reinterpret_cast<const float2*>(biasb + col);
            float2 v0 = make_float2(acc[mi][ni][0] + bb.x, acc[mi][ni][1] + bb.y);
            float2 v1 = make_float2(acc[mi][ni][2] + bb.x, acc[mi][ni][3] + bb.y);
            *reinterpret_cast<float2*>(yb + (size_t)(mi * 16 + lr) * OUT_DIM + col)     = v0;
            *reinterpret_cast<float2*>(yb + (size_t)(mi * 16 + lr + 8) * OUT_DIM + col) = v1;
        }
    }
}

// ---------------------------------------------------------------------------
extern "C" void kernel_launch(void* const* d_in, const int* in_sizes, int n_in,
                              void* d_out, int out_size)
{
    const float* x      = (const float*)d_in[0];
    const float* W      = (const float*)d_in[1];
    const float* bias   = (const float*)d_in[2];
    const float* w1a    = (const float*)d_in[3];
    const float* w1b    = (const float*)d_in[4];
    const float* w2a    = (const float*)d_in[5];
    const float* w2b    = (const float*)d_in[6];
    const float* scalar = (const float*)d_in[7];
    float* y = (float*)d_out;

    (void)in_sizes; (void)n_in; (void)out_size;

    static bool attr_set = false;
    if (!attr_set) {
        cudaFuncSetAttribute(gemm_f16_pipe,
                             cudaFuncAttributeMaxDynamicSharedMemorySize, SMEM_BYTES);
        attr_set = true;
    }

    prep_fused_kernel<<<FUSED_BLOCKS, 256>>>(x, W, w1a, w1b, w2a, w2b, scalar);
    gemm_f16_pipe<<<dim3(OUT_DIM / 128, M_TOTAL / 128), 256, SMEM_BYTES>>>(bias, y);
}